// round 13
// baseline (speedup 1.0000x reference)
#include <cuda_runtime.h>
#include <math.h>

#define N_POINTS 16384
#define N_PAIRS  65536

#define T_SUPER  16
#define N_SUPER  136                         // upper-tri 1024x1024 supertiles
#define SUBS_PER_SUPER 4                     // 4 j-quarters; all 1024 i per CTA
#define HEAVY_BLOCKS (N_SUPER * SUBS_PER_SUPER)  // 544
#define PAIR_BLOCKS  64
#define NBLOCKS  (HEAVY_BLOCKS + PAIR_BLOCKS)    // 608
#define JTILE 256

typedef unsigned int u32;

// ---- device scratch (no allocation allowed) ----------------------------------
__device__ float g_part_p[HEAVY_BLOCKS];
__device__ float g_kld_p[PAIR_BLOCKS];
__device__ float g_pair_p[PAIR_BLOCKS];
__device__ float g_pij_p[PAIR_BLOCKS];
__device__ unsigned int g_ticket = 0;

// ---- reductions ----------------------------------------------------------------
__device__ __forceinline__ float warp_reduce(float v) {
    #pragma unroll
    for (int o = 16; o > 0; o >>= 1) v += __shfl_xor_sync(0xffffffffu, v, o);
    return v;
}
__device__ __forceinline__ float block_reduce(float v, float* smem) {
    v = warp_reduce(v);
    int lane = threadIdx.x & 31, wid = threadIdx.x >> 5;
    if (lane == 0) smem[wid] = v;
    __syncthreads();
    v = (threadIdx.x < 8) ? smem[threadIdx.x] : 0.0f;
    if (wid == 0) {
        #pragma unroll
        for (int o = 4; o > 0; o >>= 1) v += __shfl_xor_sync(0xffffffffu, v, o);
    }
    return v;  // valid in thread 0
}

// ---- reparam helper: x = eps*exp(0.5*lv) + mu ----------------------------------
__device__ __forceinline__ float2 reparam_pt(const float* __restrict__ mu,
                                             const float* __restrict__ lv,
                                             const float* __restrict__ eps,
                                             int idx) {
    float2 m = ((const float2*)mu)[idx];
    float2 l = ((const float2*)lv)[idx];
    float2 e = ((const float2*)eps)[idx];
    float2 x;
    x.x = fmaf(e.x, __expf(0.5f * l.x), m.x);
    x.y = fmaf(e.y, __expf(0.5f * l.y), m.y);
    return x;
}

// one scalar newton term: d = (b + h) + cx*xx + cy*xy; acc += ~1/d
// 2 FFMA + 1 FADD + 1 IADD(seed) + 2 FFMA
__device__ __forceinline__ void term1(float cx, float cy, float b,
                                      float xx, float xy, float h, float& acc) {
    float d = fmaf(cx, xx, fmaf(cy, xy, b + h));
    float y = __uint_as_float(0x7EF127EAu - __float_as_uint(d));
    acc = fmaf(y, fmaf(-d, y, 2.0f), acc);
}

// ---- single fused kernel --------------------------------------------------------
__global__ __launch_bounds__(256, 5)
void k_main(const float* __restrict__ pij,
            const int*   __restrict__ ii,
            const int*   __restrict__ jj,
            const float* __restrict__ mu,
            const float* __restrict__ lv,
            const float* __restrict__ epsf,
            const float* __restrict__ epsi,
            const float* __restrict__ epsj,
            float* __restrict__ out) {
    __shared__ __align__(16) float4 s_j[JTILE];   // per j: (cx=-2xjx, cy=-2xjy, b=1+|xj|^2, 0)
    __shared__ float  sred[8];
    __shared__ float  sred1[8];
    __shared__ double sdd[256];
    __shared__ unsigned int s_last;

    const int bid = blockIdx.x;
    const int tid = threadIdx.x;

    if (bid < HEAVY_BLOCKS) {
        // -------- heavy path: supertile s (1024 i), j-quarter sub (256 j) --------
        int s = bid >> 2;
        int sub = bid & 3;
        int a = 0, rem = s;
        while (rem >= T_SUPER - a) { rem -= T_SUPER - a; a++; }
        int b = a + rem;
        int i0 = a * 1024;
        int j0 = b * 1024 + sub * JTILE;
        float wt = (a == b) ? 1.0f : 2.0f;

        // build j-tile in shared (reparam on the fly)
        {
            float2 xj = reparam_pt(mu, lv, epsf, j0 + tid);
            s_j[tid] = make_float4(-2.0f * xj.x, -2.0f * xj.y,
                                   fmaf(xj.x, xj.x, fmaf(xj.y, xj.y, 1.0f)), 0.0f);
        }

        // FOUR i-chains per thread (1024 i per CTA)
        float2 x0 = reparam_pt(mu, lv, epsf, i0 + tid);
        float2 x1 = reparam_pt(mu, lv, epsf, i0 + 256 + tid);
        float2 x2 = reparam_pt(mu, lv, epsf, i0 + 512 + tid);
        float2 x3 = reparam_pt(mu, lv, epsf, i0 + 768 + tid);
        float h0 = fmaf(x0.x, x0.x, x0.y * x0.y);   // |xi|^2
        float h1 = fmaf(x1.x, x1.x, x1.y * x1.y);
        float h2 = fmaf(x2.x, x2.x, x2.y * x2.y);
        float h3 = fmaf(x3.x, x3.x, x3.y * x3.y);
        float acc0 = 0.0f, acc1 = 0.0f, acc2 = 0.0f, acc3 = 0.0f;

        __syncthreads();

        #pragma unroll 4
        for (int p = 0; p < JTILE; p++) {
            float4 v = s_j[p];   // LDS.128 broadcast, amortized over 4 chains
            term1(v.x, v.y, v.z, x0.x, x0.y, h0, acc0);
            term1(v.x, v.y, v.z, x1.x, x1.y, h1, acc1);
            term1(v.x, v.y, v.z, x2.x, x2.y, h2, acc2);
            term1(v.x, v.y, v.z, x3.x, x3.y, h3, acc3);
        }

        float total = (acc0 + acc1) + (acc2 + acc3);
        float sres = block_reduce(total, sred);
        if (tid == 0) g_part_p[bid] = sres * wt;
    } else {
        // -------- pairs path + KLD slice -----------------------------------------
        int pb = bid - HEAVY_BLOCKS;
        float term = 0.0f, psum = 0.0f;
        int base = pb * 1024;
        #pragma unroll
        for (int r = 0; r < 4; r++) {
            int p = base + r * 256 + tid;
            int ai = ii[p], bi = jj[p];
            float2 ma = ((const float2*)mu)[ai];
            float2 la = ((const float2*)lv)[ai];
            float2 ea = ((const float2*)epsi)[p];
            float2 mb = ((const float2*)mu)[bi];
            float2 lb = ((const float2*)lv)[bi];
            float2 eb = ((const float2*)epsj)[p];
            float xax = fmaf(ea.x, __expf(0.5f * la.x), ma.x);
            float xay = fmaf(ea.y, __expf(0.5f * la.y), ma.y);
            float xbx = fmaf(eb.x, __expf(0.5f * lb.x), mb.x);
            float xby = fmaf(eb.y, __expf(0.5f * lb.y), mb.y);
            float da = xax - xbx, db = xay - xby;
            float d2 = fmaf(da, da, db * db);
            float pv = pij[p];
            // pij*(log pij - log qij) = pij*(log pij + log(1+d2)) + pij*log(part)
            term += pv * (logf(pv) + log1pf(d2));
            psum += pv;
        }
        // KLD slice: 256 points per pair-block (64 * 256 = 16384)
        float kld;
        {
            int idx = pb * 256 + tid;
            float2 m = ((const float2*)mu)[idx];
            float2 l = ((const float2*)lv)[idx];
            kld = (1.0f + l.x - m.x * m.x - __expf(l.x))
                + (1.0f + l.y - m.y * m.y - __expf(l.y));
        }
        float s0 = block_reduce(term, sred);
        __syncthreads();
        float s1 = block_reduce(psum, sred1);
        __syncthreads();
        float s2 = block_reduce(kld, sred);
        if (tid == 0) {
            g_pair_p[pb] = s0;
            g_pij_p[pb]  = s1;
            g_kld_p[pb]  = s2;
        }
    }

    // -------- fused final: last CTA reduces everything ----------------------------
    __threadfence();
    if (tid == 0) s_last = atomicAdd(&g_ticket, 1u);
    __syncthreads();
    if (s_last == NBLOCKS - 1) {
        __threadfence();
        double part = 0.0, kld = 0.0, pair = 0.0, pijs = 0.0;
        for (int t = tid; t < HEAVY_BLOCKS; t += 256) part += (double)g_part_p[t];
        if (tid < PAIR_BLOCKS) {
            kld  = (double)g_kld_p[tid];
            pair = (double)g_pair_p[tid];
            pijs = (double)g_pij_p[tid];
        }
        double vals[4] = {part, kld, pair, pijs};
        double res[4];
        #pragma unroll
        for (int k = 0; k < 4; k++) {
            sdd[tid] = vals[k];
            __syncthreads();
            for (int o = 128; o > 0; o >>= 1) {
                if (tid < o) sdd[tid] += sdd[tid + o];
                __syncthreads();
            }
            res[k] = sdd[0];
            __syncthreads();
        }
        if (tid == 0) {
            double partv = res[0] - (double)N_POINTS;   // remove diagonal
            double loss = res[2] + res[3] * log(partv) + 1e-7 * (-0.5 * res[1]);
            out[0] = (float)loss;
            g_ticket = 0;   // reset for next graph replay
        }
    }
}

// -----------------------------------------------------------------------------
extern "C" void kernel_launch(void* const* d_in, const int* in_sizes, int n_in,
                              void* d_out, int out_size) {
    const float* pij      = (const float*)d_in[0];
    const int*   i_idx    = (const int*)  d_in[1];
    const int*   j_idx    = (const int*)  d_in[2];
    const float* mu_w     = (const float*)d_in[3];
    const float* lv_w     = (const float*)d_in[4];
    const float* eps_full = (const float*)d_in[5];
    const float* eps_i    = (const float*)d_in[6];
    const float* eps_j    = (const float*)d_in[7];
    float* out = (float*)d_out;

    k_main<<<NBLOCKS, 256>>>(pij, i_idx, j_idx, mu_w, lv_w,
                             eps_full, eps_i, eps_j, out);
}

// round 14
// speedup vs baseline: 1.2011x; 1.2011x over previous
#include <cuda_runtime.h>
#include <cuda_fp16.h>
#include <math.h>

#define N_POINTS 16384
#define N_PAIRS  65536

#define T_SUPER  16
#define N_SUPER  136                         // upper-tri 1024x1024 supertiles
#define SUBS_PER_SUPER 4                     // 4 j-quarters; all 1024 i per CTA
#define HEAVY_BLOCKS (N_SUPER * SUBS_PER_SUPER)  // 544
#define PAIR_BLOCKS  64
#define NBLOCKS  (HEAVY_BLOCKS + PAIR_BLOCKS)    // 608
#define JTILE 256
#define JPAIRS (JTILE / 2)                   // 128 j-pairs (2 j's per half2)

typedef unsigned int u32;

// ---- device scratch (no allocation allowed) ----------------------------------
__device__ float g_part_p[HEAVY_BLOCKS];
__device__ float g_kld_p[PAIR_BLOCKS];
__device__ float g_pair_p[PAIR_BLOCKS];
__device__ float g_pij_p[PAIR_BLOCKS];
__device__ unsigned int g_ticket = 0;

// ---- half2 bit helpers ---------------------------------------------------------
__device__ __forceinline__ __half2 u2h(u32 u) {
    __half2 h; *reinterpret_cast<u32*>(&h) = u; return h;
}
__device__ __forceinline__ u32 h2u(__half2 h) {
    return *reinterpret_cast<u32*>(&h);
}

// ---- reductions ----------------------------------------------------------------
__device__ __forceinline__ float warp_reduce(float v) {
    #pragma unroll
    for (int o = 16; o > 0; o >>= 1) v += __shfl_xor_sync(0xffffffffu, v, o);
    return v;
}
__device__ __forceinline__ float block_reduce(float v, float* smem) {
    v = warp_reduce(v);
    int lane = threadIdx.x & 31, wid = threadIdx.x >> 5;
    if (lane == 0) smem[wid] = v;
    __syncthreads();
    v = (threadIdx.x < 8) ? smem[threadIdx.x] : 0.0f;
    if (wid == 0) {
        #pragma unroll
        for (int o = 4; o > 0; o >>= 1) v += __shfl_xor_sync(0xffffffffu, v, o);
    }
    return v;  // valid in thread 0
}

// ---- reparam helper: x = eps*exp(0.5*lv) + mu ----------------------------------
__device__ __forceinline__ float2 reparam_pt(const float* __restrict__ mu,
                                             const float* __restrict__ lv,
                                             const float* __restrict__ eps,
                                             int idx) {
    float2 m = ((const float2*)mu)[idx];
    float2 l = ((const float2*)lv)[idx];
    float2 e = ((const float2*)eps)[idx];
    float2 x;
    x.x = fmaf(e.x, __expf(0.5f * l.x), m.x);
    x.y = fmaf(e.y, __expf(0.5f * l.y), m.y);
    return x;
}

// ---- single fused kernel --------------------------------------------------------
__global__ __launch_bounds__(256, 5)
void k_main(const float* __restrict__ pij,
            const int*   __restrict__ ii,
            const int*   __restrict__ jj,
            const float* __restrict__ mu,
            const float* __restrict__ lv,
            const float* __restrict__ epsf,
            const float* __restrict__ epsi,
            const float* __restrict__ epsj,
            float* __restrict__ out) {
    __shared__ __align__(16) uint2 s_cc[JPAIRS];  // per j-pair: (cx2, cy2) half2 bits, c=-2x
    __shared__ __align__(16) u32   s_bb[JPAIRS];  // per j-pair: b2 = (1+|xj|^2) half2 bits
    __shared__ float  sred[8];
    __shared__ float  sred1[8];
    __shared__ double sdd[256];
    __shared__ unsigned int s_last;

    const int bid = blockIdx.x;
    const int tid = threadIdx.x;

    if (bid < HEAVY_BLOCKS) {
        // -------- heavy path: supertile s (1024 i), j-quarter sub (256 j) --------
        int s = bid >> 2;
        int sub = bid & 3;
        int a = 0, rem = s;
        while (rem >= T_SUPER - a) { rem -= T_SUPER - a; a++; }
        int b = a + rem;
        int i0 = a * 1024;
        int j0 = b * 1024 + sub * JTILE;
        float wt = (a == b) ? 1.0f : 2.0f;

        // build j-tile in shared: thread tid owns j-pair tid (points j0+2t, j0+2t+1)
        if (tid < JPAIRS) {
            int q = (j0 >> 1) + tid;   // float4 index (2 points per float4)
            float4 m = ((const float4*)mu)[q];
            float4 l = ((const float4*)lv)[q];
            float4 e = ((const float4*)epsf)[q];
            float x0x = fmaf(e.x, __expf(0.5f * l.x), m.x);
            float x0y = fmaf(e.y, __expf(0.5f * l.y), m.y);
            float x1x = fmaf(e.z, __expf(0.5f * l.z), m.z);
            float x1y = fmaf(e.w, __expf(0.5f * l.w), m.w);
            __half2 cx2 = __floats2half2_rn(-2.0f * x0x, -2.0f * x1x);
            __half2 cy2 = __floats2half2_rn(-2.0f * x0y, -2.0f * x1y);
            __half2 b2  = __floats2half2_rn(fmaf(x0x, x0x, fmaf(x0y, x0y, 1.0f)),
                                            fmaf(x1x, x1x, fmaf(x1y, x1y, 1.0f)));
            s_cc[tid] = make_uint2(h2u(cx2), h2u(cy2));
            s_bb[tid] = h2u(b2);
        }

        // FOUR i-chains per thread (1024 i per CTA), broadcast into half2
        float2 x0 = reparam_pt(mu, lv, epsf, i0 + tid);
        float2 x1 = reparam_pt(mu, lv, epsf, i0 + 256 + tid);
        float2 x2 = reparam_pt(mu, lv, epsf, i0 + 512 + tid);
        float2 x3 = reparam_pt(mu, lv, epsf, i0 + 768 + tid);
        __half2 xx0 = __float2half2_rn(x0.x), xy0 = __float2half2_rn(x0.y);
        __half2 xx1 = __float2half2_rn(x1.x), xy1 = __float2half2_rn(x1.y);
        __half2 xx2 = __float2half2_rn(x2.x), xy2 = __float2half2_rn(x2.y);
        __half2 xx3 = __float2half2_rn(x3.x), xy3 = __float2half2_rn(x3.y);
        __half2 h0 = __float2half2_rn(fmaf(x0.x, x0.x, x0.y * x0.y));
        __half2 h1 = __float2half2_rn(fmaf(x1.x, x1.x, x1.y * x1.y));
        __half2 h2 = __float2half2_rn(fmaf(x2.x, x2.x, x2.y * x2.y));
        __half2 h3 = __float2half2_rn(fmaf(x3.x, x3.x, x3.y * x3.y));
        const __half2 TWOH = u2h(0x40004000u);   // (2.0h, 2.0h)

        float accf0 = 0.0f, accf1 = 0.0f, accf2 = 0.0f, accf3 = 0.0f;

        __syncthreads();

        // groups of 8 j-pairs; fp16 accumulators flushed to fp32 each group
        #pragma unroll 2
        for (int g = 0; g < JPAIRS / 8; g++) {
            __half2 a0 = u2h(0u), a1 = u2h(0u), a2 = u2h(0u), a3 = u2h(0u);
            #pragma unroll
            for (int k = 0; k < 8; k++) {
                int p = g * 8 + k;
                uint2 cc = s_cc[p];      // LDS.64 broadcast
                u32 bbu = s_bb[p];       // LDS.32 broadcast
                __half2 cx2 = u2h(cc.x), cy2 = u2h(cc.y), b2 = u2h(bbu);
                // d = (b + h) + cx*xx + cy*xy = 1 + dist^2 >= 1 (both halves)
                __half2 d0 = __hfma2(cx2, xx0, __hfma2(cy2, xy0, __hadd2(b2, h0)));
                __half2 y0 = u2h(0xF789F789u - h2u(d0));   // ~ -(1/d) per half
                a0 = __hfma2(y0, __hfma2(d0, y0, TWOH), a0);  // acc -= newton(1/d)

                __half2 d1 = __hfma2(cx2, xx1, __hfma2(cy2, xy1, __hadd2(b2, h1)));
                __half2 y1 = u2h(0xF789F789u - h2u(d1));
                a1 = __hfma2(y1, __hfma2(d1, y1, TWOH), a1);

                __half2 d2 = __hfma2(cx2, xx2, __hfma2(cy2, xy2, __hadd2(b2, h2)));
                __half2 y2 = u2h(0xF789F789u - h2u(d2));
                a2 = __hfma2(y2, __hfma2(d2, y2, TWOH), a2);

                __half2 d3 = __hfma2(cx2, xx3, __hfma2(cy2, xy3, __hadd2(b2, h3)));
                __half2 y3 = u2h(0xF789F789u - h2u(d3));
                a3 = __hfma2(y3, __hfma2(d3, y3, TWOH), a3);
            }
            float2 f0 = __half22float2(a0);
            float2 f1 = __half22float2(a1);
            float2 f2 = __half22float2(a2);
            float2 f3 = __half22float2(a3);
            accf0 += f0.x + f0.y;
            accf1 += f1.x + f1.y;
            accf2 += f2.x + f2.y;
            accf3 += f3.x + f3.y;
        }

        // accs hold negated sums
        float total = -(((accf0 + accf1) + (accf2 + accf3)));
        float sres = block_reduce(total, sred);
        if (tid == 0) g_part_p[bid] = sres * wt;
    } else {
        // -------- pairs path + KLD slice (fp32, accuracy-critical) ---------------
        int pb = bid - HEAVY_BLOCKS;
        float term = 0.0f, psum = 0.0f;
        int base = pb * 1024;
        #pragma unroll
        for (int r = 0; r < 4; r++) {
            int p = base + r * 256 + tid;
            int ai = ii[p], bi = jj[p];
            float2 ma = ((const float2*)mu)[ai];
            float2 la = ((const float2*)lv)[ai];
            float2 ea = ((const float2*)epsi)[p];
            float2 mb = ((const float2*)mu)[bi];
            float2 lb = ((const float2*)lv)[bi];
            float2 eb = ((const float2*)epsj)[p];
            float xax = fmaf(ea.x, __expf(0.5f * la.x), ma.x);
            float xay = fmaf(ea.y, __expf(0.5f * la.y), ma.y);
            float xbx = fmaf(eb.x, __expf(0.5f * lb.x), mb.x);
            float xby = fmaf(eb.y, __expf(0.5f * lb.y), mb.y);
            float da = xax - xbx, db = xay - xby;
            float d2 = fmaf(da, da, db * db);
            float pv = pij[p];
            // pij*(log pij - log qij) = pij*(log pij + log(1+d2)) + pij*log(part)
            term += pv * (logf(pv) + log1pf(d2));
            psum += pv;
        }
        // KLD slice: 256 points per pair-block (64 * 256 = 16384)
        float kld;
        {
            int idx = pb * 256 + tid;
            float2 m = ((const float2*)mu)[idx];
            float2 l = ((const float2*)lv)[idx];
            kld = (1.0f + l.x - m.x * m.x - __expf(l.x))
                + (1.0f + l.y - m.y * m.y - __expf(l.y));
        }
        float s0 = block_reduce(term, sred);
        __syncthreads();
        float s1 = block_reduce(psum, sred1);
        __syncthreads();
        float s2 = block_reduce(kld, sred);
        if (tid == 0) {
            g_pair_p[pb] = s0;
            g_pij_p[pb]  = s1;
            g_kld_p[pb]  = s2;
        }
    }

    // -------- fused final: last CTA reduces everything ----------------------------
    __threadfence();
    if (tid == 0) s_last = atomicAdd(&g_ticket, 1u);
    __syncthreads();
    if (s_last == NBLOCKS - 1) {
        __threadfence();
        double part = 0.0, kld = 0.0, pair = 0.0, pijs = 0.0;
        for (int t = tid; t < HEAVY_BLOCKS; t += 256) part += (double)g_part_p[t];
        if (tid < PAIR_BLOCKS) {
            kld  = (double)g_kld_p[tid];
            pair = (double)g_pair_p[tid];
            pijs = (double)g_pij_p[tid];
        }
        double vals[4] = {part, kld, pair, pijs};
        double res[4];
        #pragma unroll
        for (int k = 0; k < 4; k++) {
            sdd[tid] = vals[k];
            __syncthreads();
            for (int o = 128; o > 0; o >>= 1) {
                if (tid < o) sdd[tid] += sdd[tid + o];
                __syncthreads();
            }
            res[k] = sdd[0];
            __syncthreads();
        }
        if (tid == 0) {
            double partv = res[0] - (double)N_POINTS;   // remove diagonal
            double loss = res[2] + res[3] * log(partv) + 1e-7 * (-0.5 * res[1]);
            out[0] = (float)loss;
            g_ticket = 0;   // reset for next graph replay
        }
    }
}

// -----------------------------------------------------------------------------
extern "C" void kernel_launch(void* const* d_in, const int* in_sizes, int n_in,
                              void* d_out, int out_size) {
    const float* pij      = (const float*)d_in[0];
    const int*   i_idx    = (const int*)  d_in[1];
    const int*   j_idx    = (const int*)  d_in[2];
    const float* mu_w     = (const float*)d_in[3];
    const float* lv_w     = (const float*)d_in[4];
    const float* eps_full = (const float*)d_in[5];
    const float* eps_i    = (const float*)d_in[6];
    const float* eps_j    = (const float*)d_in[7];
    float* out = (float*)d_out;

    k_main<<<NBLOCKS, 256>>>(pij, i_idx, j_idx, mu_w, lv_w,
                             eps_full, eps_i, eps_j, out);
}

// round 15
// speedup vs baseline: 1.2070x; 1.0049x over previous
#include <cuda_runtime.h>
#include <cuda_fp16.h>
#include <math.h>

#define N_POINTS 16384
#define N_PAIRS  65536

#define T_SUPER  16
#define N_SUPER  136                         // upper-tri 1024x1024 supertiles
#define SUBS_PER_SUPER 8                     // 8 j-eighths; all 1024 i per CTA
#define HEAVY_BLOCKS (N_SUPER * SUBS_PER_SUPER)  // 1088
#define PAIR_BLOCKS  64
#define NBLOCKS  (HEAVY_BLOCKS + PAIR_BLOCKS)    // 1152
#define JTILE 128
#define JPAIRS (JTILE / 2)                   // 64 j-pairs (2 j's per half2)

typedef unsigned int u32;

// ---- device scratch (no allocation allowed) ----------------------------------
__device__ float g_part_p[HEAVY_BLOCKS];
__device__ float g_kld_p[PAIR_BLOCKS];
__device__ float g_pair_p[PAIR_BLOCKS];
__device__ float g_pij_p[PAIR_BLOCKS];
__device__ unsigned int g_ticket = 0;

// ---- half2 bit helpers ---------------------------------------------------------
__device__ __forceinline__ __half2 u2h(u32 u) {
    __half2 h; *reinterpret_cast<u32*>(&h) = u; return h;
}
__device__ __forceinline__ u32 h2u(__half2 h) {
    return *reinterpret_cast<u32*>(&h);
}

// ---- reductions ----------------------------------------------------------------
__device__ __forceinline__ float warp_reduce(float v) {
    #pragma unroll
    for (int o = 16; o > 0; o >>= 1) v += __shfl_xor_sync(0xffffffffu, v, o);
    return v;
}
__device__ __forceinline__ float block_reduce(float v, float* smem) {
    v = warp_reduce(v);
    int lane = threadIdx.x & 31, wid = threadIdx.x >> 5;
    if (lane == 0) smem[wid] = v;
    __syncthreads();
    v = (threadIdx.x < 8) ? smem[threadIdx.x] : 0.0f;
    if (wid == 0) {
        #pragma unroll
        for (int o = 4; o > 0; o >>= 1) v += __shfl_xor_sync(0xffffffffu, v, o);
    }
    return v;  // valid in thread 0
}

// ---- reparam helper: x = eps*exp(0.5*lv) + mu ----------------------------------
__device__ __forceinline__ float2 reparam_pt(const float* __restrict__ mu,
                                             const float* __restrict__ lv,
                                             const float* __restrict__ eps,
                                             int idx) {
    float2 m = ((const float2*)mu)[idx];
    float2 l = ((const float2*)lv)[idx];
    float2 e = ((const float2*)eps)[idx];
    float2 x;
    x.x = fmaf(e.x, __expf(0.5f * l.x), m.x);
    x.y = fmaf(e.y, __expf(0.5f * l.y), m.y);
    return x;
}

// ---- single fused kernel --------------------------------------------------------
__global__ __launch_bounds__(256, 5)
void k_main(const float* __restrict__ pij,
            const int*   __restrict__ ii,
            const int*   __restrict__ jj,
            const float* __restrict__ mu,
            const float* __restrict__ lv,
            const float* __restrict__ epsf,
            const float* __restrict__ epsi,
            const float* __restrict__ epsj,
            float* __restrict__ out) {
    __shared__ __align__(16) uint2 s_cc[JPAIRS];  // per j-pair: (cx2, cy2) half2 bits, c=-2x
    __shared__ __align__(16) u32   s_bb[JPAIRS];  // per j-pair: b2 = (1+|xj|^2) half2 bits
    __shared__ float  sred[8];
    __shared__ float  sred1[8];
    __shared__ double sdd[256];
    __shared__ unsigned int s_last;

    const int bid = blockIdx.x;
    const int tid = threadIdx.x;

    if (bid < HEAVY_BLOCKS) {
        // -------- heavy path: supertile s (1024 i), j-eighth sub (128 j) ---------
        int s = bid >> 3;
        int sub = bid & 7;
        int a = 0, rem = s;
        while (rem >= T_SUPER - a) { rem -= T_SUPER - a; a++; }
        int b = a + rem;
        int i0 = a * 1024;
        int j0 = b * 1024 + sub * JTILE;
        float wt = (a == b) ? 1.0f : 2.0f;

        // build j-tile in shared: thread tid owns j-pair tid (points j0+2t, j0+2t+1)
        if (tid < JPAIRS) {
            int q = (j0 >> 1) + tid;   // float4 index (2 points per float4)
            float4 m = ((const float4*)mu)[q];
            float4 l = ((const float4*)lv)[q];
            float4 e = ((const float4*)epsf)[q];
            float x0x = fmaf(e.x, __expf(0.5f * l.x), m.x);
            float x0y = fmaf(e.y, __expf(0.5f * l.y), m.y);
            float x1x = fmaf(e.z, __expf(0.5f * l.z), m.z);
            float x1y = fmaf(e.w, __expf(0.5f * l.w), m.w);
            __half2 cx2 = __floats2half2_rn(-2.0f * x0x, -2.0f * x1x);
            __half2 cy2 = __floats2half2_rn(-2.0f * x0y, -2.0f * x1y);
            __half2 b2  = __floats2half2_rn(fmaf(x0x, x0x, fmaf(x0y, x0y, 1.0f)),
                                            fmaf(x1x, x1x, fmaf(x1y, x1y, 1.0f)));
            s_cc[tid] = make_uint2(h2u(cx2), h2u(cy2));
            s_bb[tid] = h2u(b2);
        }

        // FOUR i-chains per thread (1024 i per CTA), broadcast into half2
        float2 x0 = reparam_pt(mu, lv, epsf, i0 + tid);
        float2 x1 = reparam_pt(mu, lv, epsf, i0 + 256 + tid);
        float2 x2 = reparam_pt(mu, lv, epsf, i0 + 512 + tid);
        float2 x3 = reparam_pt(mu, lv, epsf, i0 + 768 + tid);
        __half2 xx0 = __float2half2_rn(x0.x), xy0 = __float2half2_rn(x0.y);
        __half2 xx1 = __float2half2_rn(x1.x), xy1 = __float2half2_rn(x1.y);
        __half2 xx2 = __float2half2_rn(x2.x), xy2 = __float2half2_rn(x2.y);
        __half2 xx3 = __float2half2_rn(x3.x), xy3 = __float2half2_rn(x3.y);
        __half2 h0 = __float2half2_rn(fmaf(x0.x, x0.x, x0.y * x0.y));
        __half2 h1 = __float2half2_rn(fmaf(x1.x, x1.x, x1.y * x1.y));
        __half2 h2 = __float2half2_rn(fmaf(x2.x, x2.x, x2.y * x2.y));
        __half2 h3 = __float2half2_rn(fmaf(x3.x, x3.x, x3.y * x3.y));
        const __half2 TWOH = u2h(0x40004000u);   // (2.0h, 2.0h)

        float accf0 = 0.0f, accf1 = 0.0f, accf2 = 0.0f, accf3 = 0.0f;

        __syncthreads();

        // groups of 8 j-pairs; fp16 accumulators flushed to fp32 each group
        #pragma unroll 2
        for (int g = 0; g < JPAIRS / 8; g++) {
            __half2 a0 = u2h(0u), a1 = u2h(0u), a2 = u2h(0u), a3 = u2h(0u);
            #pragma unroll
            for (int k = 0; k < 8; k++) {
                int p = g * 8 + k;
                uint2 cc = s_cc[p];      // LDS.64 broadcast
                u32 bbu = s_bb[p];       // LDS.32 broadcast
                __half2 cx2 = u2h(cc.x), cy2 = u2h(cc.y), b2 = u2h(bbu);
                // d = (b + h) + cx*xx + cy*xy = 1 + dist^2 >= 1 (both halves)
                __half2 d0 = __hfma2(cx2, xx0, __hfma2(cy2, xy0, __hadd2(b2, h0)));
                __half2 y0 = u2h(0xF789F789u - h2u(d0));   // ~ -(1/d) per half
                a0 = __hfma2(y0, __hfma2(d0, y0, TWOH), a0);  // acc -= newton(1/d)

                __half2 d1 = __hfma2(cx2, xx1, __hfma2(cy2, xy1, __hadd2(b2, h1)));
                __half2 y1 = u2h(0xF789F789u - h2u(d1));
                a1 = __hfma2(y1, __hfma2(d1, y1, TWOH), a1);

                __half2 d2 = __hfma2(cx2, xx2, __hfma2(cy2, xy2, __hadd2(b2, h2)));
                __half2 y2 = u2h(0xF789F789u - h2u(d2));
                a2 = __hfma2(y2, __hfma2(d2, y2, TWOH), a2);

                __half2 d3 = __hfma2(cx2, xx3, __hfma2(cy2, xy3, __hadd2(b2, h3)));
                __half2 y3 = u2h(0xF789F789u - h2u(d3));
                a3 = __hfma2(y3, __hfma2(d3, y3, TWOH), a3);
            }
            float2 f0 = __half22float2(a0);
            float2 f1 = __half22float2(a1);
            float2 f2 = __half22float2(a2);
            float2 f3 = __half22float2(a3);
            accf0 += f0.x + f0.y;
            accf1 += f1.x + f1.y;
            accf2 += f2.x + f2.y;
            accf3 += f3.x + f3.y;
        }

        // accs hold negated sums
        float total = -(((accf0 + accf1) + (accf2 + accf3)));
        float sres = block_reduce(total, sred);
        if (tid == 0) g_part_p[bid] = sres * wt;
    } else {
        // -------- pairs path + KLD slice (fp32, accuracy-critical) ---------------
        int pb = bid - HEAVY_BLOCKS;
        float term = 0.0f, psum = 0.0f;
        int base = pb * 1024;
        #pragma unroll
        for (int r = 0; r < 4; r++) {
            int p = base + r * 256 + tid;
            int ai = ii[p], bi = jj[p];
            float2 ma = ((const float2*)mu)[ai];
            float2 la = ((const float2*)lv)[ai];
            float2 ea = ((const float2*)epsi)[p];
            float2 mb = ((const float2*)mu)[bi];
            float2 lb = ((const float2*)lv)[bi];
            float2 eb = ((const float2*)epsj)[p];
            float xax = fmaf(ea.x, __expf(0.5f * la.x), ma.x);
            float xay = fmaf(ea.y, __expf(0.5f * la.y), ma.y);
            float xbx = fmaf(eb.x, __expf(0.5f * lb.x), mb.x);
            float xby = fmaf(eb.y, __expf(0.5f * lb.y), mb.y);
            float da = xax - xbx, db = xay - xby;
            float d2 = fmaf(da, da, db * db);
            float pv = pij[p];
            // pij*(log pij - log qij) = pij*(log pij + log(1+d2)) + pij*log(part)
            term += pv * (logf(pv) + log1pf(d2));
            psum += pv;
        }
        // KLD slice: 256 points per pair-block (64 * 256 = 16384)
        float kld;
        {
            int idx = pb * 256 + tid;
            float2 m = ((const float2*)mu)[idx];
            float2 l = ((const float2*)lv)[idx];
            kld = (1.0f + l.x - m.x * m.x - __expf(l.x))
                + (1.0f + l.y - m.y * m.y - __expf(l.y));
        }
        float s0 = block_reduce(term, sred);
        __syncthreads();
        float s1 = block_reduce(psum, sred1);
        __syncthreads();
        float s2 = block_reduce(kld, sred);
        if (tid == 0) {
            g_pair_p[pb] = s0;
            g_pij_p[pb]  = s1;
            g_kld_p[pb]  = s2;
        }
    }

    // -------- fused final: last CTA reduces everything ----------------------------
    __threadfence();
    if (tid == 0) s_last = atomicAdd(&g_ticket, 1u);
    __syncthreads();
    if (s_last == NBLOCKS - 1) {
        __threadfence();
        double part = 0.0, kld = 0.0, pair = 0.0, pijs = 0.0;
        for (int t = tid; t < HEAVY_BLOCKS; t += 256) part += (double)g_part_p[t];
        if (tid < PAIR_BLOCKS) {
            kld  = (double)g_kld_p[tid];
            pair = (double)g_pair_p[tid];
            pijs = (double)g_pij_p[tid];
        }
        double vals[4] = {part, kld, pair, pijs};
        double res[4];
        #pragma unroll
        for (int k = 0; k < 4; k++) {
            sdd[tid] = vals[k];
            __syncthreads();
            for (int o = 128; o > 0; o >>= 1) {
                if (tid < o) sdd[tid] += sdd[tid + o];
                __syncthreads();
            }
            res[k] = sdd[0];
            __syncthreads();
        }
        if (tid == 0) {
            double partv = res[0] - (double)N_POINTS;   // remove diagonal
            double loss = res[2] + res[3] * log(partv) + 1e-7 * (-0.5 * res[1]);
            out[0] = (float)loss;
            g_ticket = 0;   // reset for next graph replay
        }
    }
}

// -----------------------------------------------------------------------------
extern "C" void kernel_launch(void* const* d_in, const int* in_sizes, int n_in,
                              void* d_out, int out_size) {
    const float* pij      = (const float*)d_in[0];
    const int*   i_idx    = (const int*)  d_in[1];
    const int*   j_idx    = (const int*)  d_in[2];
    const float* mu_w     = (const float*)d_in[3];
    const float* lv_w     = (const float*)d_in[4];
    const float* eps_full = (const float*)d_in[5];
    const float* eps_i    = (const float*)d_in[6];
    const float* eps_j    = (const float*)d_in[7];
    float* out = (float*)d_out;

    k_main<<<NBLOCKS, 256>>>(pij, i_idx, j_idx, mu_w, lv_w,
                             eps_full, eps_i, eps_j, out);
}

// round 16
// speedup vs baseline: 1.2742x; 1.0557x over previous
#include <cuda_runtime.h>
#include <cuda_fp16.h>
#include <math.h>

#define N_POINTS 16384
#define N_PAIRS  65536

#define T_SUPER  16
#define N_SUPER  136                         // upper-tri 1024x1024 supertiles
#define SUBS_PER_SUPER 8                     // 8 j-eighths; all 1024 i per CTA
#define HEAVY_BLOCKS (N_SUPER * SUBS_PER_SUPER)  // 1088
#define PAIR_BLOCKS  64
#define NBLOCKS  (HEAVY_BLOCKS + PAIR_BLOCKS)    // 1152
#define JTILE 128
#define JPAIRS (JTILE / 2)                   // 64 j-pairs (2 j's per half2)

typedef unsigned int u32;

// ---- device scratch (no allocation allowed) ----------------------------------
__device__ float g_part_p[HEAVY_BLOCKS];
__device__ float g_kld_p[PAIR_BLOCKS];
__device__ float g_pair_p[PAIR_BLOCKS];
__device__ float g_pij_p[PAIR_BLOCKS];
__device__ unsigned int g_ticket = 0;

// ---- half2 <-> u32 (setup only; hot loop is pure asm) ---------------------------
__device__ __forceinline__ u32 h2u(__half2 h) {
    u32 u; asm("mov.b32 %0, %1;" : "=r"(u) : "r"(*reinterpret_cast<u32*>(&h)));
    return *reinterpret_cast<u32*>(&h);
}
__device__ __forceinline__ float2 acc_to_f2(u32 a) {
    __half2 h = *reinterpret_cast<__half2*>(&a);
    return __half22float2(h);
}

// one j-pair x one i-chain: 2 terms, 6 instructions, zero casts.
// d = (b + h) + cy*xy + cx*xx = 1 + dist^2 (per half); acc -= ~1/d (negated newton)
__device__ __forceinline__ void term2(u32 cx2, u32 cy2, u32 b2,
                                      u32 xx2, u32 xy2, u32 h2,
                                      u32 two2, u32& acc) {
    asm("{\n\t"
        ".reg .b32 t, d, y;\n\t"
        "add.rn.f16x2 t, %1, %2;\n\t"        // b + h
        "fma.rn.f16x2 t, %3, %4, t;\n\t"     // + cy*xy
        "fma.rn.f16x2 d, %5, %6, t;\n\t"     // + cx*xx
        "sub.u32 y, 0xF789F789, d;\n\t"      // magic seed: y ~ -(1/d), both halves
        "fma.rn.f16x2 t, d, y, %7;\n\t"      // 2 - d*|y|  (signs: d*y+2)
        "fma.rn.f16x2 %0, y, t, %0;\n\t"     // acc += y*t  (= acc - newton(1/d))
        "}"
        : "+r"(acc)
        : "r"(b2), "r"(h2), "r"(cy2), "r"(xy2), "r"(cx2), "r"(xx2), "r"(two2));
}

// ---- reductions ----------------------------------------------------------------
__device__ __forceinline__ float warp_reduce(float v) {
    #pragma unroll
    for (int o = 16; o > 0; o >>= 1) v += __shfl_xor_sync(0xffffffffu, v, o);
    return v;
}
__device__ __forceinline__ float block_reduce(float v, float* smem) {
    v = warp_reduce(v);
    int lane = threadIdx.x & 31, wid = threadIdx.x >> 5;
    if (lane == 0) smem[wid] = v;
    __syncthreads();
    v = (threadIdx.x < 8) ? smem[threadIdx.x] : 0.0f;
    if (wid == 0) {
        #pragma unroll
        for (int o = 4; o > 0; o >>= 1) v += __shfl_xor_sync(0xffffffffu, v, o);
    }
    return v;  // valid in thread 0
}

// ---- reparam helper: x = eps*exp(0.5*lv) + mu ----------------------------------
__device__ __forceinline__ float2 reparam_pt(const float* __restrict__ mu,
                                             const float* __restrict__ lv,
                                             const float* __restrict__ eps,
                                             int idx) {
    float2 m = ((const float2*)mu)[idx];
    float2 l = ((const float2*)lv)[idx];
    float2 e = ((const float2*)eps)[idx];
    float2 x;
    x.x = fmaf(e.x, __expf(0.5f * l.x), m.x);
    x.y = fmaf(e.y, __expf(0.5f * l.y), m.y);
    return x;
}

// ---- single fused kernel --------------------------------------------------------
__global__ __launch_bounds__(256, 5)
void k_main(const float* __restrict__ pij,
            const int*   __restrict__ ii,
            const int*   __restrict__ jj,
            const float* __restrict__ mu,
            const float* __restrict__ lv,
            const float* __restrict__ epsf,
            const float* __restrict__ epsi,
            const float* __restrict__ epsj,
            float* __restrict__ out) {
    __shared__ __align__(16) uint4 s_j[JPAIRS];  // per j-pair: (cx2, cy2, b2, pad) half2 bits
    __shared__ float  sred[8];
    __shared__ float  sred1[8];
    __shared__ double sdd[256];
    __shared__ unsigned int s_last;

    const int bid = blockIdx.x;
    const int tid = threadIdx.x;

    if (bid < HEAVY_BLOCKS) {
        // -------- heavy path: supertile s (1024 i), j-eighth sub (128 j) ---------
        int s = bid >> 3;
        int sub = bid & 7;
        int a = 0, rem = s;
        while (rem >= T_SUPER - a) { rem -= T_SUPER - a; a++; }
        int b = a + rem;
        int i0 = a * 1024;
        int j0 = b * 1024 + sub * JTILE;
        float wt = (a == b) ? 1.0f : 2.0f;

        // build j-tile in shared: thread tid owns j-pair tid (points j0+2t, j0+2t+1)
        if (tid < JPAIRS) {
            int q = (j0 >> 1) + tid;   // float4 index (2 points per float4)
            float4 m = ((const float4*)mu)[q];
            float4 l = ((const float4*)lv)[q];
            float4 e = ((const float4*)epsf)[q];
            float x0x = fmaf(e.x, __expf(0.5f * l.x), m.x);
            float x0y = fmaf(e.y, __expf(0.5f * l.y), m.y);
            float x1x = fmaf(e.z, __expf(0.5f * l.z), m.z);
            float x1y = fmaf(e.w, __expf(0.5f * l.w), m.w);
            __half2 cx2 = __floats2half2_rn(-2.0f * x0x, -2.0f * x1x);
            __half2 cy2 = __floats2half2_rn(-2.0f * x0y, -2.0f * x1y);
            __half2 b2  = __floats2half2_rn(fmaf(x0x, x0x, fmaf(x0y, x0y, 1.0f)),
                                            fmaf(x1x, x1x, fmaf(x1y, x1y, 1.0f)));
            s_j[tid] = make_uint4(h2u(cx2), h2u(cy2), h2u(b2), 0u);
        }

        // FOUR i-chains per thread (1024 i per CTA), broadcast into half2 (u32 bits)
        float2 x0 = reparam_pt(mu, lv, epsf, i0 + tid);
        float2 x1 = reparam_pt(mu, lv, epsf, i0 + 256 + tid);
        float2 x2 = reparam_pt(mu, lv, epsf, i0 + 512 + tid);
        float2 x3 = reparam_pt(mu, lv, epsf, i0 + 768 + tid);
        u32 xx0 = h2u(__float2half2_rn(x0.x)), xy0 = h2u(__float2half2_rn(x0.y));
        u32 xx1 = h2u(__float2half2_rn(x1.x)), xy1 = h2u(__float2half2_rn(x1.y));
        u32 xx2 = h2u(__float2half2_rn(x2.x)), xy2 = h2u(__float2half2_rn(x2.y));
        u32 xx3 = h2u(__float2half2_rn(x3.x)), xy3 = h2u(__float2half2_rn(x3.y));
        u32 h0 = h2u(__float2half2_rn(fmaf(x0.x, x0.x, x0.y * x0.y)));
        u32 h1 = h2u(__float2half2_rn(fmaf(x1.x, x1.x, x1.y * x1.y)));
        u32 h2_ = h2u(__float2half2_rn(fmaf(x2.x, x2.x, x2.y * x2.y)));
        u32 h3 = h2u(__float2half2_rn(fmaf(x3.x, x3.x, x3.y * x3.y)));
        const u32 TWO2 = 0x40004000u;   // (2.0h, 2.0h)

        float accf0 = 0.0f, accf1 = 0.0f, accf2 = 0.0f, accf3 = 0.0f;

        __syncthreads();

        // groups of 8 j-pairs; fp16 accumulators flushed to fp32 each group
        #pragma unroll 2
        for (int g = 0; g < JPAIRS / 8; g++) {
            u32 a0 = 0u, a1 = 0u, a2 = 0u, a3 = 0u;
            #pragma unroll
            for (int k = 0; k < 8; k++) {
                uint4 v = s_j[g * 8 + k];   // single LDS.128 broadcast
                term2(v.x, v.y, v.z, xx0, xy0, h0, TWO2, a0);
                term2(v.x, v.y, v.z, xx1, xy1, h1, TWO2, a1);
                term2(v.x, v.y, v.z, xx2, xy2, h2_, TWO2, a2);
                term2(v.x, v.y, v.z, xx3, xy3, h3, TWO2, a3);
            }
            float2 f0 = acc_to_f2(a0);
            float2 f1 = acc_to_f2(a1);
            float2 f2 = acc_to_f2(a2);
            float2 f3 = acc_to_f2(a3);
            accf0 += f0.x + f0.y;
            accf1 += f1.x + f1.y;
            accf2 += f2.x + f2.y;
            accf3 += f3.x + f3.y;
        }

        // accs hold negated sums
        float total = -(((accf0 + accf1) + (accf2 + accf3)));
        float sres = block_reduce(total, sred);
        if (tid == 0) g_part_p[bid] = sres * wt;
    } else {
        // -------- pairs path + KLD slice (fp32, accuracy-critical) ---------------
        int pb = bid - HEAVY_BLOCKS;
        float term = 0.0f, psum = 0.0f;
        int base = pb * 1024;
        #pragma unroll
        for (int r = 0; r < 4; r++) {
            int p = base + r * 256 + tid;
            int ai = ii[p], bi = jj[p];
            float2 ma = ((const float2*)mu)[ai];
            float2 la = ((const float2*)lv)[ai];
            float2 ea = ((const float2*)epsi)[p];
            float2 mb = ((const float2*)mu)[bi];
            float2 lb = ((const float2*)lv)[bi];
            float2 eb = ((const float2*)epsj)[p];
            float xax = fmaf(ea.x, __expf(0.5f * la.x), ma.x);
            float xay = fmaf(ea.y, __expf(0.5f * la.y), ma.y);
            float xbx = fmaf(eb.x, __expf(0.5f * lb.x), mb.x);
            float xby = fmaf(eb.y, __expf(0.5f * lb.y), mb.y);
            float da = xax - xbx, db = xay - xby;
            float d2 = fmaf(da, da, db * db);
            float pv = pij[p];
            // pij*(log pij - log qij) = pij*(log pij + log(1+d2)) + pij*log(part)
            term += pv * (logf(pv) + log1pf(d2));
            psum += pv;
        }
        // KLD slice: 256 points per pair-block (64 * 256 = 16384)
        float kld;
        {
            int idx = pb * 256 + tid;
            float2 m = ((const float2*)mu)[idx];
            float2 l = ((const float2*)lv)[idx];
            kld = (1.0f + l.x - m.x * m.x - __expf(l.x))
                + (1.0f + l.y - m.y * m.y - __expf(l.y));
        }
        float s0 = block_reduce(term, sred);
        __syncthreads();
        float s1 = block_reduce(psum, sred1);
        __syncthreads();
        float s2 = block_reduce(kld, sred);
        if (tid == 0) {
            g_pair_p[pb] = s0;
            g_pij_p[pb]  = s1;
            g_kld_p[pb]  = s2;
        }
    }

    // -------- fused final: last CTA reduces everything ----------------------------
    __threadfence();
    if (tid == 0) s_last = atomicAdd(&g_ticket, 1u);
    __syncthreads();
    if (s_last == NBLOCKS - 1) {
        __threadfence();
        double part = 0.0, kld = 0.0, pair = 0.0, pijs = 0.0;
        for (int t = tid; t < HEAVY_BLOCKS; t += 256) part += (double)g_part_p[t];
        if (tid < PAIR_BLOCKS) {
            kld  = (double)g_kld_p[tid];
            pair = (double)g_pair_p[tid];
            pijs = (double)g_pij_p[tid];
        }
        double vals[4] = {part, kld, pair, pijs};
        double res[4];
        #pragma unroll
        for (int k = 0; k < 4; k++) {
            sdd[tid] = vals[k];
            __syncthreads();
            for (int o = 128; o > 0; o >>= 1) {
                if (tid < o) sdd[tid] += sdd[tid + o];
                __syncthreads();
            }
            res[k] = sdd[0];
            __syncthreads();
        }
        if (tid == 0) {
            double partv = res[0] - (double)N_POINTS;   // remove diagonal
            double loss = res[2] + res[3] * log(partv) + 1e-7 * (-0.5 * res[1]);
            out[0] = (float)loss;
            g_ticket = 0;   // reset for next graph replay
        }
    }
}

// -----------------------------------------------------------------------------
extern "C" void kernel_launch(void* const* d_in, const int* in_sizes, int n_in,
                              void* d_out, int out_size) {
    const float* pij      = (const float*)d_in[0];
    const int*   i_idx    = (const int*)  d_in[1];
    const int*   j_idx    = (const int*)  d_in[2];
    const float* mu_w     = (const float*)d_in[3];
    const float* lv_w     = (const float*)d_in[4];
    const float* eps_full = (const float*)d_in[5];
    const float* eps_i    = (const float*)d_in[6];
    const float* eps_j    = (const float*)d_in[7];
    float* out = (float*)d_out;

    k_main<<<NBLOCKS, 256>>>(pij, i_idx, j_idx, mu_w, lv_w,
                             eps_full, eps_i, eps_j, out);
}

// round 17
// speedup vs baseline: 1.3469x; 1.0571x over previous
#include <cuda_runtime.h>
#include <cuda_fp16.h>
#include <math.h>

#define N_POINTS 16384
#define N_PAIRS  65536

#define T_SUPER  16
#define N_SUPER  136                         // upper-tri 1024x1024 supertiles
#define SUBS_PER_SUPER 8                     // 8 j-eighths; all 1024 i per CTA
#define HEAVY_BLOCKS (N_SUPER * SUBS_PER_SUPER)  // 1088
#define PAIR_BLOCKS  64
#define NBLOCKS  (HEAVY_BLOCKS + PAIR_BLOCKS)    // 1152
#define JTILE 128
#define JPAIRS (JTILE / 2)                   // 64 j-pairs (2 j's per half2)

typedef unsigned int u32;

// ---- device scratch (no allocation allowed) ----------------------------------
__device__ float g_part_p[HEAVY_BLOCKS];
__device__ float g_kld_p[PAIR_BLOCKS];
__device__ float g_pair_p[PAIR_BLOCKS];
__device__ float g_pij_p[PAIR_BLOCKS];
__device__ unsigned int g_ticket = 0;

// ---- half2 <-> u32 (setup only; hot loop is pure asm) ---------------------------
__device__ __forceinline__ u32 h2u(__half2 h) {
    return *reinterpret_cast<u32*>(&h);
}
__device__ __forceinline__ float2 acc_to_f2(u32 a) {
    __half2 h = *reinterpret_cast<__half2*>(&a);
    return __half22float2(h);
}

// one j-pair x one i-chain: 2 terms, 6 instructions, zero casts.
// d = (b + h) + cy*xy + cx*xx = 1 + dist^2 (per half); acc -= ~1/d (negated newton)
__device__ __forceinline__ void term2(u32 cx2, u32 cy2, u32 b2,
                                      u32 xx2, u32 xy2, u32 h2,
                                      u32 two2, u32& acc) {
    asm("{\n\t"
        ".reg .b32 t, d, y;\n\t"
        "add.rn.f16x2 t, %1, %2;\n\t"        // b + h
        "fma.rn.f16x2 t, %3, %4, t;\n\t"     // + cy*xy
        "fma.rn.f16x2 d, %5, %6, t;\n\t"     // + cx*xx
        "sub.u32 y, 0xF789F789, d;\n\t"      // magic seed: y ~ -(1/d), both halves
        "fma.rn.f16x2 t, d, y, %7;\n\t"      // 2 - d*|y|  (signs: d*y+2)
        "fma.rn.f16x2 %0, y, t, %0;\n\t"     // acc += y*t  (= acc - newton(1/d))
        "}"
        : "+r"(acc)
        : "r"(b2), "r"(h2), "r"(cy2), "r"(xy2), "r"(cx2), "r"(xx2), "r"(two2));
}

// ---- reductions ----------------------------------------------------------------
__device__ __forceinline__ float warp_reduce(float v) {
    #pragma unroll
    for (int o = 16; o > 0; o >>= 1) v += __shfl_xor_sync(0xffffffffu, v, o);
    return v;
}
__device__ __forceinline__ float block_reduce(float v, float* smem) {
    v = warp_reduce(v);
    int lane = threadIdx.x & 31, wid = threadIdx.x >> 5;
    if (lane == 0) smem[wid] = v;
    __syncthreads();
    v = (threadIdx.x < 8) ? smem[threadIdx.x] : 0.0f;
    if (wid == 0) {
        #pragma unroll
        for (int o = 4; o > 0; o >>= 1) v += __shfl_xor_sync(0xffffffffu, v, o);
    }
    return v;  // valid in thread 0
}

// ---- reparam helper: x = eps*exp(0.5*lv) + mu ----------------------------------
__device__ __forceinline__ float2 reparam_pt(const float* __restrict__ mu,
                                             const float* __restrict__ lv,
                                             const float* __restrict__ eps,
                                             int idx) {
    float2 m = ((const float2*)mu)[idx];
    float2 l = ((const float2*)lv)[idx];
    float2 e = ((const float2*)eps)[idx];
    float2 x;
    x.x = fmaf(e.x, __expf(0.5f * l.x), m.x);
    x.y = fmaf(e.y, __expf(0.5f * l.y), m.y);
    return x;
}

// ---- single fused kernel --------------------------------------------------------
__global__ __launch_bounds__(256, 5)
void k_main(const float* __restrict__ pij,
            const int*   __restrict__ ii,
            const int*   __restrict__ jj,
            const float* __restrict__ mu,
            const float* __restrict__ lv,
            const float* __restrict__ epsf,
            const float* __restrict__ epsi,
            const float* __restrict__ epsj,
            float* __restrict__ out) {
    __shared__ __align__(16) uint4 s_j[JPAIRS];  // per j-pair: (cx2, cy2, b2, pad) half2 bits
    __shared__ float  sred[8];
    __shared__ float  sred1[8];
    __shared__ double sdd[256];
    __shared__ unsigned int s_last;

    const int bid = blockIdx.x;
    const int tid = threadIdx.x;

    if (bid < HEAVY_BLOCKS) {
        // -------- heavy path: supertile s (1024 i), j-eighth sub (128 j) ---------
        int s = bid >> 3;
        int sub = bid & 7;
        int a = 0, rem = s;
        while (rem >= T_SUPER - a) { rem -= T_SUPER - a; a++; }
        int b = a + rem;
        int i0 = a * 1024;
        int j0 = b * 1024 + sub * JTILE;
        float wt = (a == b) ? 1.0f : 2.0f;

        // build j-tile in shared: thread tid owns j-pair tid (points j0+2t, j0+2t+1)
        if (tid < JPAIRS) {
            int q = (j0 >> 1) + tid;   // float4 index (2 points per float4)
            float4 m = ((const float4*)mu)[q];
            float4 l = ((const float4*)lv)[q];
            float4 e = ((const float4*)epsf)[q];
            float x0x = fmaf(e.x, __expf(0.5f * l.x), m.x);
            float x0y = fmaf(e.y, __expf(0.5f * l.y), m.y);
            float x1x = fmaf(e.z, __expf(0.5f * l.z), m.z);
            float x1y = fmaf(e.w, __expf(0.5f * l.w), m.w);
            __half2 cx2 = __floats2half2_rn(-2.0f * x0x, -2.0f * x1x);
            __half2 cy2 = __floats2half2_rn(-2.0f * x0y, -2.0f * x1y);
            __half2 b2  = __floats2half2_rn(fmaf(x0x, x0x, fmaf(x0y, x0y, 1.0f)),
                                            fmaf(x1x, x1x, fmaf(x1y, x1y, 1.0f)));
            s_j[tid] = make_uint4(h2u(cx2), h2u(cy2), h2u(b2), 0u);
        }

        // FOUR i-chains per thread (1024 i per CTA), broadcast into half2 (u32 bits)
        float2 x0 = reparam_pt(mu, lv, epsf, i0 + tid);
        float2 x1 = reparam_pt(mu, lv, epsf, i0 + 256 + tid);
        float2 x2 = reparam_pt(mu, lv, epsf, i0 + 512 + tid);
        float2 x3 = reparam_pt(mu, lv, epsf, i0 + 768 + tid);
        u32 xx0 = h2u(__float2half2_rn(x0.x)), xy0 = h2u(__float2half2_rn(x0.y));
        u32 xx1 = h2u(__float2half2_rn(x1.x)), xy1 = h2u(__float2half2_rn(x1.y));
        u32 xx2 = h2u(__float2half2_rn(x2.x)), xy2 = h2u(__float2half2_rn(x2.y));
        u32 xx3 = h2u(__float2half2_rn(x3.x)), xy3 = h2u(__float2half2_rn(x3.y));
        u32 h0 = h2u(__float2half2_rn(fmaf(x0.x, x0.x, x0.y * x0.y)));
        u32 h1 = h2u(__float2half2_rn(fmaf(x1.x, x1.x, x1.y * x1.y)));
        u32 h2_ = h2u(__float2half2_rn(fmaf(x2.x, x2.x, x2.y * x2.y)));
        u32 h3 = h2u(__float2half2_rn(fmaf(x3.x, x3.x, x3.y * x3.y)));
        const u32 TWO2 = 0x40004000u;   // (2.0h, 2.0h)

        // fp16 accumulators for the ENTIRE 64-pair tile (max 64 per half, safe;
        // RN rounding noise ~4e-6 relative on part — negligible). One flush at end.
        u32 a0 = 0u, a1 = 0u, a2 = 0u, a3 = 0u;

        __syncthreads();

        #pragma unroll 8
        for (int p = 0; p < JPAIRS; p++) {
            uint4 v = s_j[p];   // single LDS.128 broadcast per j-pair
            term2(v.x, v.y, v.z, xx0, xy0, h0, TWO2, a0);
            term2(v.x, v.y, v.z, xx1, xy1, h1, TWO2, a1);
            term2(v.x, v.y, v.z, xx2, xy2, h2_, TWO2, a2);
            term2(v.x, v.y, v.z, xx3, xy3, h3, TWO2, a3);
        }

        float2 f0 = acc_to_f2(a0);
        float2 f1 = acc_to_f2(a1);
        float2 f2 = acc_to_f2(a2);
        float2 f3 = acc_to_f2(a3);
        // accs hold negated sums
        float total = -(((f0.x + f0.y) + (f1.x + f1.y))
                      + ((f2.x + f2.y) + (f3.x + f3.y)));
        float sres = block_reduce(total, sred);
        if (tid == 0) g_part_p[bid] = sres * wt;
    } else {
        // -------- pairs path + KLD slice (fp32, accuracy-critical) ---------------
        int pb = bid - HEAVY_BLOCKS;
        float term = 0.0f, psum = 0.0f;
        int base = pb * 1024;
        #pragma unroll
        for (int r = 0; r < 4; r++) {
            int p = base + r * 256 + tid;
            int ai = ii[p], bi = jj[p];
            float2 ma = ((const float2*)mu)[ai];
            float2 la = ((const float2*)lv)[ai];
            float2 ea = ((const float2*)epsi)[p];
            float2 mb = ((const float2*)mu)[bi];
            float2 lb = ((const float2*)lv)[bi];
            float2 eb = ((const float2*)epsj)[p];
            float xax = fmaf(ea.x, __expf(0.5f * la.x), ma.x);
            float xay = fmaf(ea.y, __expf(0.5f * la.y), ma.y);
            float xbx = fmaf(eb.x, __expf(0.5f * lb.x), mb.x);
            float xby = fmaf(eb.y, __expf(0.5f * lb.y), mb.y);
            float da = xax - xbx, db = xay - xby;
            float d2 = fmaf(da, da, db * db);
            float pv = pij[p];
            // pij*(log pij - log qij) = pij*(log pij + log(1+d2)) + pij*log(part)
            term += pv * (logf(pv) + log1pf(d2));
            psum += pv;
        }
        // KLD slice: 256 points per pair-block (64 * 256 = 16384)
        float kld;
        {
            int idx = pb * 256 + tid;
            float2 m = ((const float2*)mu)[idx];
            float2 l = ((const float2*)lv)[idx];
            kld = (1.0f + l.x - m.x * m.x - __expf(l.x))
                + (1.0f + l.y - m.y * m.y - __expf(l.y));
        }
        float s0 = block_reduce(term, sred);
        __syncthreads();
        float s1 = block_reduce(psum, sred1);
        __syncthreads();
        float s2 = block_reduce(kld, sred);
        if (tid == 0) {
            g_pair_p[pb] = s0;
            g_pij_p[pb]  = s1;
            g_kld_p[pb]  = s2;
        }
    }

    // -------- fused final: last CTA reduces everything ----------------------------
    __threadfence();
    if (tid == 0) s_last = atomicAdd(&g_ticket, 1u);
    __syncthreads();
    if (s_last == NBLOCKS - 1) {
        __threadfence();
        double part = 0.0, kld = 0.0, pair = 0.0, pijs = 0.0;
        for (int t = tid; t < HEAVY_BLOCKS; t += 256) part += (double)g_part_p[t];
        if (tid < PAIR_BLOCKS) {
            kld  = (double)g_kld_p[tid];
            pair = (double)g_pair_p[tid];
            pijs = (double)g_pij_p[tid];
        }
        double vals[4] = {part, kld, pair, pijs};
        double res[4];
        #pragma unroll
        for (int k = 0; k < 4; k++) {
            sdd[tid] = vals[k];
            __syncthreads();
            for (int o = 128; o > 0; o >>= 1) {
                if (tid < o) sdd[tid] += sdd[tid + o];
                __syncthreads();
            }
            res[k] = sdd[0];
            __syncthreads();
        }
        if (tid == 0) {
            double partv = res[0] - (double)N_POINTS;   // remove diagonal
            double loss = res[2] + res[3] * log(partv) + 1e-7 * (-0.5 * res[1]);
            out[0] = (float)loss;
            g_ticket = 0;   // reset for next graph replay
        }
    }
}

// -----------------------------------------------------------------------------
extern "C" void kernel_launch(void* const* d_in, const int* in_sizes, int n_in,
                              void* d_out, int out_size) {
    const float* pij      = (const float*)d_in[0];
    const int*   i_idx    = (const int*)  d_in[1];
    const int*   j_idx    = (const int*)  d_in[2];
    const float* mu_w     = (const float*)d_in[3];
    const float* lv_w     = (const float*)d_in[4];
    const float* eps_full = (const float*)d_in[5];
    const float* eps_i    = (const float*)d_in[6];
    const float* eps_j    = (const float*)d_in[7];
    float* out = (float*)d_out;

    k_main<<<NBLOCKS, 256>>>(pij, i_idx, j_idx, mu_w, lv_w,
                             eps_full, eps_i, eps_j, out);
}